// round 3
// baseline (speedup 1.0000x reference)
#include <cuda_runtime.h>

#define NL   24
#define TSEQ 256    // scan length = original batch dim
#define NPOS 96     // positions (LSTM batch); only 48..95 survive
#define NSEQ 48

__device__ float g_z[TSEQ * 1536];
__device__ float g_h[TSEQ * 1000];

#define LOG2E 1.4426950408889634f

__device__ __forceinline__ float fexp2_(float x) {
    float r; asm("ex2.approx.ftz.f32 %0, %1;" : "=f"(r) : "f"(x)); return r;
}
__device__ __forceinline__ float frcp_(float x) {
    float r; asm("rcp.approx.ftz.f32 %0, %1;" : "=f"(r) : "f"(x)); return r;
}
__device__ __forceinline__ float sigm_(float x) {
    return frcp_(1.f + fexp2_(-LOG2E * x));
}
__device__ __forceinline__ float tanh_(float x) {
    return fmaf(2.f, frcp_(1.f + fexp2_(-2.f * LOG2E * x)), -1.f);
}

// One warp runs one direction of one layer's recurrence over T=256.
// lane l handles gate rows l and l+32:
//   lanes 0..15 : i_j (row j),   g_j (row 32+j)
//   lanes 16..31: f_j (row j),   o_j (row 32+j)   [rows 16..31 / 48..63]
// h[16] replicated in every lane's registers; rebuilt via 16 shuffles per step.
__device__ __forceinline__ void lstm_chain(
    const float* __restrict__ xg,    // [T][64] for this dir
    const float* __restrict__ whh,   // [64][16] for this layer+dir
    float* __restrict__ outp,        // nxt + dir*16, row stride 32
    int rev, int lane)
{
    float w0[16], w1[16];
#pragma unroll
    for (int k = 0; k < 16; k++) {
        w0[k] = whh[lane * 16 + k];
        w1[k] = whh[(lane + 32) * 16 + k];
    }
    float h[16];
#pragma unroll
    for (int k = 0; k < 16; k++) h[k] = 0.f;
    float c = 0.f;
    const bool lo = lane < 16;
    // act1: lanes<16 need tanh(g), lanes>=16 sigmoid(o); unified:
    //   act1 = s2 * rcp(1 + exp2(-m2*log2e*x)) + a2
    const float m2 = lo ? 2.f : 1.f;
    const float s2 = lo ? 2.f : 1.f;
    const float a2 = lo ? -1.f : 0.f;

    int t  = rev ? (TSEQ - 1) : 0;
    const int dt = rev ? -1 : 1;
    float xa0 = xg[t * 64 + lane];
    float xa1 = xg[t * 64 + lane + 32];

    for (int s = 0; s < TSEQ; s++) {
        float a00 = xa0, a01 = 0.f, a02 = 0.f, a03 = 0.f;
        float a10 = xa1, a11 = 0.f, a12 = 0.f, a13 = 0.f;
#pragma unroll
        for (int k = 0; k < 16; k += 4) {
            a00 = fmaf(w0[k],     h[k],     a00); a10 = fmaf(w1[k],     h[k],     a10);
            a01 = fmaf(w0[k + 1], h[k + 1], a01); a11 = fmaf(w1[k + 1], h[k + 1], a11);
            a02 = fmaf(w0[k + 2], h[k + 2], a02); a12 = fmaf(w1[k + 2], h[k + 2], a12);
            a03 = fmaf(w0[k + 3], h[k + 3], a03); a13 = fmaf(w1[k + 3], h[k + 3], a13);
        }
        float a0 = (a00 + a01) + (a02 + a03);
        float a1 = (a10 + a11) + (a12 + a13);

        const int tn = t + dt;
        if (s + 1 < TSEQ) {               // prefetch next step's xg
            xa0 = xg[tn * 64 + lane];
            xa1 = xg[tn * 64 + lane + 32];
        }

        float act0 = sigm_(a0);                                          // sig(i) / sig(f)
        float act1 = fmaf(s2, frcp_(1.f + fexp2_(-m2 * LOG2E * a1)), a2); // tanh(g) / sig(o)

        float p0 = __shfl_xor_sync(0xffffffffu, act0, 16);
        float p1 = __shfl_xor_sync(0xffffffffu, act1, 16);
        float iv = lo ? act0 : p0;
        float fv = lo ? p0 : act0;
        float gv = lo ? act1 : p1;
        float ov = lo ? p1 : act1;
        c = fmaf(fv, c, iv * gv);
        float hn = ov * tanh_(c);
        if (lo) outp[t * 32 + lane] = hn;
#pragma unroll
        for (int k = 0; k < 16; k++) h[k] = __shfl_sync(0xffffffffu, hn, k);
        t = tn;
    }
}

__global__ void __launch_bounds__(256, 1)
lstm_kernel(const float* __restrict__ x,
            const float* __restrict__ Wih0, const float* __restrict__ Wih1,
            const float* __restrict__ Whh1, const float* __restrict__ bih1,
            const float* __restrict__ bhh1,
            const float* __restrict__ Wih2, const float* __restrict__ Whh2,
            const float* __restrict__ bih2, const float* __restrict__ bhh2)
{
    extern __shared__ float sm[];
    float* s_xg = sm;                          // [2][256][64]
    float* bufA = sm + 2 * TSEQ * 64;          // [256][32]
    float* bufB = bufA + TSEQ * 32;            // [256][32]
    const int n2 = blockIdx.x;                 // 0..47
    const int n  = 48 + n2;                    // surviving position
    const int tid = threadIdx.x;

    // x: (256, 1, 96) row-major; sequence step t uses x[t*96 + n]
    for (int t = tid; t < TSEQ; t += 256) bufA[t * 32] = x[t * NPOS + n];
    __syncthreads();

    float* cur = bufA;
    float* nxt = bufB;

    const int combo = tid & 127, half = tid >> 7;
    const int dirA = combo >> 6, gate = combo & 63;

    // ---------------- stack 1 (input dim 1 then 32) ----------------
    for (int l = 0; l < NL; l++) {
        {   // phase A: xg[dir][t][gate] = bih + bhh + Wih . x_t
            const int bidx = (l * 2 + dirA) * 64 + gate;
            const float b = bih1[bidx] + bhh1[bidx];
            float* xgd = s_xg + dirA * TSEQ * 64;
            if (l == 0) {
                const float w = Wih0[dirA * 64 + gate];
                for (int t = half * 128; t < half * 128 + 128; t++)
                    xgd[t * 64 + gate] = fmaf(w, cur[t * 32], b);
            } else {
                const float4* Wv = (const float4*)(Wih1 + ((size_t)((l - 1) * 2 + dirA) * 64 + gate) * 32);
                float4 w[8];
#pragma unroll
                for (int q = 0; q < 8; q++) w[q] = Wv[q];
                for (int t = half * 128; t < half * 128 + 128; t++) {
                    const float4* xv = (const float4*)(cur + t * 32);
                    float acc = b;
#pragma unroll
                    for (int q = 0; q < 8; q++) {
                        float4 xq = xv[q];
                        acc = fmaf(w[q].x, xq.x, acc);
                        acc = fmaf(w[q].y, xq.y, acc);
                        acc = fmaf(w[q].z, xq.z, acc);
                        acc = fmaf(w[q].w, xq.w, acc);
                    }
                    xgd[t * 64 + gate] = acc;
                }
            }
        }
        __syncthreads();
        if (tid < 64) {
            const int dir = tid >> 5, lane = tid & 31;
            lstm_chain(s_xg + dir * TSEQ * 64,
                       Whh1 + (size_t)(l * 2 + dir) * 1024,
                       nxt + dir * 16, dir, lane);
        }
        __syncthreads();
        float* tmp = cur; cur = nxt; nxt = tmp;
    }

    // Save x1 (stack-1 output for this n) into g_z; residual added later.
    for (int i = tid; i < TSEQ * 32; i += 256) {
        const int b_ = i >> 5, c_ = i & 31;
        g_z[(size_t)b_ * 1536 + n2 * 32 + c_] = cur[i];
    }

    // ---------------- stack 2 (input dim 32) ----------------
    for (int l = 0; l < NL; l++) {
        {
            const int bidx = (l * 2 + dirA) * 64 + gate;
            const float b = bih2[bidx] + bhh2[bidx];
            float* xgd = s_xg + dirA * TSEQ * 64;
            const float4* Wv = (const float4*)(Wih2 + ((size_t)(l * 2 + dirA) * 64 + gate) * 32);
            float4 w[8];
#pragma unroll
            for (int q = 0; q < 8; q++) w[q] = Wv[q];
            for (int t = half * 128; t < half * 128 + 128; t++) {
                const float4* xv = (const float4*)(cur + t * 32);
                float acc = b;
#pragma unroll
                for (int q = 0; q < 8; q++) {
                    float4 xq = xv[q];
                    acc = fmaf(w[q].x, xq.x, acc);
                    acc = fmaf(w[q].y, xq.y, acc);
                    acc = fmaf(w[q].z, xq.z, acc);
                    acc = fmaf(w[q].w, xq.w, acc);
                }
                xgd[t * 64 + gate] = acc;
            }
        }
        __syncthreads();
        if (tid < 64) {
            const int dir = tid >> 5, lane = tid & 31;
            lstm_chain(s_xg + dir * TSEQ * 64,
                       Whh2 + (size_t)(l * 2 + dir) * 1024,
                       nxt + dir * 16, dir, lane);
        }
        __syncthreads();
        float* tmp = cur; cur = nxt; nxt = tmp;
    }

    // z = h2 + x1  (x1 written above by this same thread at the same indices)
    for (int i = tid; i < TSEQ * 32; i += 256) {
        const int b_ = i >> 5, c_ = i & 31;
        const size_t idx = (size_t)b_ * 1536 + n2 * 32 + c_;
        g_z[idx] = g_z[idx] + cur[i];
    }
}

// hidden = relu(Z @ W1^T + b1) ; Z:(256,1536), W1:(1000,1536)
__global__ void __launch_bounds__(256)
fc1_kernel(const float* __restrict__ w1, const float* __restrict__ b1)
{
    __shared__ float As[32][33];
    __shared__ float Bs[32][33];
    const int bm = blockIdx.x * 32;
    const int bn = blockIdx.y * 32;
    const int tid = threadIdx.x;
    const int tr = tid >> 5;          // 0..7
    const int tc = tid & 31;          // 0..31
    float acc[4] = {0.f, 0.f, 0.f, 0.f};
    for (int k0 = 0; k0 < 1536; k0 += 32) {
#pragma unroll
        for (int i = 0; i < 4; i++) {
            int r = tr * 4 + i;
            As[r][tc] = g_z[(size_t)(bm + r) * 1536 + k0 + tc];
            int nidx = bn + r;
            Bs[r][tc] = (nidx < 1000) ? w1[(size_t)nidx * 1536 + k0 + tc] : 0.f;
        }
        __syncthreads();
#pragma unroll
        for (int k = 0; k < 32; k++) {
            float bv = Bs[tc][k];
#pragma unroll
            for (int i = 0; i < 4; i++) acc[i] = fmaf(As[tr * 4 + i][k], bv, acc[i]);
        }
        __syncthreads();
    }
    const int nidx = bn + tc;
    if (nidx < 1000) {
        float bb = b1[nidx];
#pragma unroll
        for (int i = 0; i < 4; i++)
            g_h[(size_t)(bm + tr * 4 + i) * 1000 + nidx] = fmaxf(acc[i] + bb, 0.f);
    }
}

// out = hidden @ W2^T + b2 ; W2:(48,1000)
__global__ void __launch_bounds__(256)
fc2_kernel(const float* __restrict__ w2, const float* __restrict__ b2,
           float* __restrict__ out)
{
    __shared__ float sh[1000];
    const int nb = blockIdx.x;
    const int tid = threadIdx.x;
    for (int i = tid; i < 1000; i += 256) sh[i] = g_h[(size_t)nb * 1000 + i];
    __syncthreads();
    const int wid = tid >> 5, lane = tid & 31;
    for (int j = wid; j < 48; j += 8) {
        const float* wr = w2 + j * 1000;
        float acc = 0.f;
        for (int k = lane; k < 1000; k += 32) acc = fmaf(sh[k], wr[k], acc);
#pragma unroll
        for (int off = 16; off; off >>= 1) acc += __shfl_xor_sync(0xffffffffu, acc, off);
        if (lane == 0) out[nb * 48 + j] = acc + b2[j];
    }
}

extern "C" void kernel_launch(void* const* d_in, const int* in_sizes, int n_in,
                              void* d_out, int out_size)
{
    const float* x    = (const float*)d_in[0];
    const float* Wih0 = (const float*)d_in[1];
    const float* Wih1 = (const float*)d_in[2];
    const float* Whh1 = (const float*)d_in[3];
    const float* bih1 = (const float*)d_in[4];
    const float* bhh1 = (const float*)d_in[5];
    const float* Wih2 = (const float*)d_in[6];
    const float* Whh2 = (const float*)d_in[7];
    const float* bih2 = (const float*)d_in[8];
    const float* bhh2 = (const float*)d_in[9];
    const float* w1   = (const float*)d_in[10];
    const float* b1   = (const float*)d_in[11];
    const float* w2   = (const float*)d_in[12];
    const float* b2   = (const float*)d_in[13];
    float* out = (float*)d_out;

    const size_t smem = (size_t)(2 * TSEQ * 64 + 2 * TSEQ * 32) * sizeof(float); // 196608 B
    static int configured = -1;
    cudaFuncSetAttribute(lstm_kernel, cudaFuncAttributeMaxDynamicSharedMemorySize, (int)smem);
    (void)configured;

    lstm_kernel<<<NSEQ, 256, smem>>>(x, Wih0, Wih1, Whh1, bih1, bhh1,
                                     Wih2, Whh2, bih2, bhh2);
    fc1_kernel<<<dim3(8, 32), 256>>>(w1, b1);
    fc2_kernel<<<TSEQ, 256>>>(w2, b2, out);
}

// round 4
// speedup vs baseline: 1.0762x; 1.0762x over previous
#include <cuda_runtime.h>

#define NL   24
#define TSEQ 256    // scan length = original batch dim
#define NPOS 96     // positions; only 48..95 survive into stack 2
#define NSEQ 48

__device__ float g_z[TSEQ * 1536];
__device__ float g_h[TSEQ * 1000];

#define LOG2E 1.4426950408889634f

typedef unsigned long long u64;

__device__ __forceinline__ u64 pk2(float lo, float hi) {
    u64 r; asm("mov.b64 %0, {%1, %2};" : "=l"(r) : "f"(lo), "f"(hi)); return r;
}
__device__ __forceinline__ void unpk2(u64 v, float& lo, float& hi) {
    asm("mov.b64 {%0, %1}, %2;" : "=f"(lo), "=f"(hi) : "l"(v));
}
__device__ __forceinline__ u64 fma2_(u64 a, u64 b, u64 c) {
    u64 d; asm("fma.rn.f32x2 %0, %1, %2, %3;" : "=l"(d) : "l"(a), "l"(b), "l"(c)); return d;
}
__device__ __forceinline__ u64 add2_(u64 a, u64 b) {
    u64 d; asm("add.rn.f32x2 %0, %1, %2;" : "=l"(d) : "l"(a), "l"(b)); return d;
}

__device__ __forceinline__ float fexp2_(float x) {
    float r; asm("ex2.approx.ftz.f32 %0, %1;" : "=f"(r) : "f"(x)); return r;
}
__device__ __forceinline__ float frcp_(float x) {
    float r; asm("rcp.approx.ftz.f32 %0, %1;" : "=f"(r) : "f"(x)); return r;
}
__device__ __forceinline__ float sigm_(float x) {
    return frcp_(1.f + fexp2_(-LOG2E * x));
}
__device__ __forceinline__ float tanh_(float x) {
    return fmaf(2.f, frcp_(1.f + fexp2_(-2.f * LOG2E * x)), -1.f);
}

// gate row g (0..63) lives in xg[t][ (g&31)*2 + (g>>5) ]  -> lane's pair (l, l+32) adjacent
__device__ __forceinline__ int remap_(int g) { return ((g & 31) << 1) | (g >> 5); }

// One warp runs one direction of one layer's recurrence over T=256.
// lane l<16 : rows l (i_l) and l+32 (g_l); lane 16+l : rows 16+l (f_l), 48+l (o_l).
// h kept in a 16-float smem scratch, read back as packed pairs each step.
__device__ __forceinline__ void lstm_chain(
    const float* __restrict__ xg,    // [T][64] interleaved per remap_
    const float* __restrict__ whh,   // [64][16] for this layer+dir
    float* __restrict__ s_h,         // 16-float scratch (per warp)
    float* __restrict__ outp,        // nxt + dir*16, row stride 32
    int rev, int lane)
{
    const int row0 = lane, row1 = lane + 32;
    u64 w0[8], w1[8];
#pragma unroll
    for (int k = 0; k < 8; k++) {
        w0[k] = pk2(whh[row0 * 16 + 2 * k], whh[row0 * 16 + 2 * k + 1]);
        w1[k] = pk2(whh[row1 * 16 + 2 * k], whh[row1 * 16 + 2 * k + 1]);
    }
    if (lane < 16) s_h[lane] = 0.f;
    __syncwarp();

    float c = 0.f;
    const bool lo = lane < 16;
    const float m2 = lo ? 2.f : 1.f;   // tanh(g) vs sigmoid(o)
    const float s2 = lo ? 2.f : 1.f;
    const float a2 = lo ? -1.f : 0.f;

    int t  = rev ? (TSEQ - 1) : 0;
    const int dt = rev ? -1 : 1;
    float2 xa = *(const float2*)(xg + t * 64 + lane * 2);
    const float2* sh2 = (const float2*)s_h;

    for (int s = 0; s < TSEQ; s++) {
        u64 hq[8];
#pragma unroll
        for (int k = 0; k < 8; k++) {
            float2 hv = sh2[k];
            hq[k] = pk2(hv.x, hv.y);
        }
        u64 p00 = fma2_(w0[0], hq[0], 0ull), p01 = fma2_(w0[1], hq[1], 0ull);
        u64 p02 = fma2_(w0[2], hq[2], 0ull), p03 = fma2_(w0[3], hq[3], 0ull);
        u64 p10 = fma2_(w1[0], hq[0], 0ull), p11 = fma2_(w1[1], hq[1], 0ull);
        u64 p12 = fma2_(w1[2], hq[2], 0ull), p13 = fma2_(w1[3], hq[3], 0ull);
        p00 = fma2_(w0[4], hq[4], p00); p01 = fma2_(w0[5], hq[5], p01);
        p02 = fma2_(w0[6], hq[6], p02); p03 = fma2_(w0[7], hq[7], p03);
        p10 = fma2_(w1[4], hq[4], p10); p11 = fma2_(w1[5], hq[5], p11);
        p12 = fma2_(w1[6], hq[6], p12); p13 = fma2_(w1[7], hq[7], p13);
        u64 r0 = add2_(add2_(p00, p01), add2_(p02, p03));
        u64 r1 = add2_(add2_(p10, p11), add2_(p12, p13));
        float r0l, r0h, r1l, r1h;
        unpk2(r0, r0l, r0h);
        unpk2(r1, r1l, r1h);
        float a0 = (xa.x + r0l) + r0h;
        float a1 = (xa.y + r1l) + r1h;

        const int tn = t + dt;
        if (s + 1 < TSEQ)                 // prefetch next step's xg pair
            xa = *(const float2*)(xg + tn * 64 + lane * 2);

        float act0 = sigm_(a0);                                           // sig(i) / sig(f)
        float act1 = fmaf(s2, frcp_(1.f + fexp2_(-m2 * LOG2E * a1)), a2); // tanh(g) / sig(o)

        float p0 = __shfl_xor_sync(0xffffffffu, act0, 16);
        float p1 = __shfl_xor_sync(0xffffffffu, act1, 16);
        float iv = lo ? act0 : p0;
        float fv = lo ? p0 : act0;
        float gv = lo ? act1 : p1;
        float ov = lo ? p1 : act1;
        c = fmaf(fv, c, iv * gv);
        float hn = ov * tanh_(c);
        if (lo) {
            outp[t * 32 + lane] = hn;
            s_h[lane] = hn;
        }
        __syncwarp();
        t = tn;
    }
}

__global__ void __launch_bounds__(256, 1)
lstm_kernel(const float* __restrict__ x,
            const float* __restrict__ Wih0, const float* __restrict__ Wih1,
            const float* __restrict__ Whh1, const float* __restrict__ bih1,
            const float* __restrict__ bhh1,
            const float* __restrict__ Wih2, const float* __restrict__ Whh2,
            const float* __restrict__ bih2, const float* __restrict__ bhh2)
{
    extern __shared__ float sm[];
    float* s_xg = sm;                          // [2][256][64]
    float* bufA = sm + 2 * TSEQ * 64;          // [256][32]
    float* bufB = bufA + TSEQ * 32;            // [256][32]
    float* s_h  = bufB + TSEQ * 32;            // [2][16]
    const int n2 = blockIdx.x;                 // 0..47
    const int n  = 48 + n2;
    const int tid = threadIdx.x;

    // x: (256, 1, 96) row-major; step t uses x[t*96 + n]
    for (int t = tid; t < TSEQ; t += 256) bufA[t * 32] = x[t * NPOS + n];
    __syncthreads();

    float* cur = bufA;
    float* nxt = bufB;

    const int combo = tid & 127, half = tid >> 7;
    const int dirA = combo >> 6, gate = combo & 63;
    const int gpos = remap_(gate);

    // ---------------- stack 1 ----------------
    for (int l = 0; l < NL; l++) {
        {   // phase A: xg[dir][t][gpos] = bih + bhh + Wih . x_t
            const int bidx = (l * 2 + dirA) * 64 + gate;
            const float b = bih1[bidx] + bhh1[bidx];
            float* xgd = s_xg + dirA * TSEQ * 64;
            if (l == 0) {
                const float w = Wih0[dirA * 64 + gate];
                for (int t = half * 128; t < half * 128 + 128; t++)
                    xgd[t * 64 + gpos] = fmaf(w, cur[t * 32], b);
            } else {
                const float2* Wv = (const float2*)(Wih1 + ((size_t)((l - 1) * 2 + dirA) * 64 + gate) * 32);
                u64 w[16];
#pragma unroll
                for (int q = 0; q < 16; q++) { float2 v = Wv[q]; w[q] = pk2(v.x, v.y); }
                for (int t = half * 128; t < half * 128 + 128; t++) {
                    const float2* xv = (const float2*)(cur + t * 32);
                    u64 a0 = 0ull, a1 = 0ull, a2v = 0ull, a3 = 0ull;
#pragma unroll
                    for (int q = 0; q < 16; q += 4) {
                        float2 x0 = xv[q], x1 = xv[q + 1], x2 = xv[q + 2], x3 = xv[q + 3];
                        a0 = fma2_(w[q],     pk2(x0.x, x0.y), a0);
                        a1 = fma2_(w[q + 1], pk2(x1.x, x1.y), a1);
                        a2v = fma2_(w[q + 2], pk2(x2.x, x2.y), a2v);
                        a3 = fma2_(w[q + 3], pk2(x3.x, x3.y), a3);
                    }
                    u64 r = add2_(add2_(a0, a1), add2_(a2v, a3));
                    float rl, rh; unpk2(r, rl, rh);
                    xgd[t * 64 + gpos] = (b + rl) + rh;
                }
            }
        }
        __syncthreads();
        if (tid < 64) {
            const int dir = tid >> 5, lane = tid & 31;
            lstm_chain(s_xg + dir * TSEQ * 64,
                       Whh1 + (size_t)(l * 2 + dir) * 1024,
                       s_h + dir * 16,
                       nxt + dir * 16, dir, lane);
        }
        __syncthreads();
        float* tmp = cur; cur = nxt; nxt = tmp;
    }

    // Save x1 into g_z (residual added after stack 2).
    for (int i = tid; i < TSEQ * 32; i += 256) {
        const int b_ = i >> 5, c_ = i & 31;
        g_z[(size_t)b_ * 1536 + n2 * 32 + c_] = cur[i];
    }

    // ---------------- stack 2 ----------------
    for (int l = 0; l < NL; l++) {
        {
            const int bidx = (l * 2 + dirA) * 64 + gate;
            const float b = bih2[bidx] + bhh2[bidx];
            float* xgd = s_xg + dirA * TSEQ * 64;
            const float2* Wv = (const float2*)(Wih2 + ((size_t)(l * 2 + dirA) * 64 + gate) * 32);
            u64 w[16];
#pragma unroll
            for (int q = 0; q < 16; q++) { float2 v = Wv[q]; w[q] = pk2(v.x, v.y); }
            for (int t = half * 128; t < half * 128 + 128; t++) {
                const float2* xv = (const float2*)(cur + t * 32);
                u64 a0 = 0ull, a1 = 0ull, a2v = 0ull, a3 = 0ull;
#pragma unroll
                for (int q = 0; q < 16; q += 4) {
                    float2 x0 = xv[q], x1 = xv[q + 1], x2 = xv[q + 2], x3 = xv[q + 3];
                    a0 = fma2_(w[q],     pk2(x0.x, x0.y), a0);
                    a1 = fma2_(w[q + 1], pk2(x1.x, x1.y), a1);
                    a2v = fma2_(w[q + 2], pk2(x2.x, x2.y), a2v);
                    a3 = fma2_(w[q + 3], pk2(x3.x, x3.y), a3);
                }
                u64 r = add2_(add2_(a0, a1), add2_(a2v, a3));
                float rl, rh; unpk2(r, rl, rh);
                xgd[t * 64 + gpos] = (b + rl) + rh;
            }
        }
        __syncthreads();
        if (tid < 64) {
            const int dir = tid >> 5, lane = tid & 31;
            lstm_chain(s_xg + dir * TSEQ * 64,
                       Whh2 + (size_t)(l * 2 + dir) * 1024,
                       s_h + dir * 16,
                       nxt + dir * 16, dir, lane);
        }
        __syncthreads();
        float* tmp = cur; cur = nxt; nxt = tmp;
    }

    // z = h2 + x1
    for (int i = tid; i < TSEQ * 32; i += 256) {
        const int b_ = i >> 5, c_ = i & 31;
        const size_t idx = (size_t)b_ * 1536 + n2 * 32 + c_;
        g_z[idx] = g_z[idx] + cur[i];
    }
}

// hidden = relu(Z @ W1^T + b1) ; Z:(256,1536), W1:(1000,1536)
__global__ void __launch_bounds__(256)
fc1_kernel(const float* __restrict__ w1, const float* __restrict__ b1)
{
    __shared__ float As[32][33];
    __shared__ float Bs[32][33];
    const int bm = blockIdx.x * 32;
    const int bn = blockIdx.y * 32;
    const int tid = threadIdx.x;
    const int tr = tid >> 5;
    const int tc = tid & 31;
    float acc[4] = {0.f, 0.f, 0.f, 0.f};
    for (int k0 = 0; k0 < 1536; k0 += 32) {
#pragma unroll
        for (int i = 0; i < 4; i++) {
            int r = tr * 4 + i;
            As[r][tc] = g_z[(size_t)(bm + r) * 1536 + k0 + tc];
            int nidx = bn + r;
            Bs[r][tc] = (nidx < 1000) ? w1[(size_t)nidx * 1536 + k0 + tc] : 0.f;
        }
        __syncthreads();
#pragma unroll
        for (int k = 0; k < 32; k++) {
            float bv = Bs[tc][k];
#pragma unroll
            for (int i = 0; i < 4; i++) acc[i] = fmaf(As[tr * 4 + i][k], bv, acc[i]);
        }
        __syncthreads();
    }
    const int nidx = bn + tc;
    if (nidx < 1000) {
        float bb = b1[nidx];
#pragma unroll
        for (int i = 0; i < 4; i++)
            g_h[(size_t)(bm + tr * 4 + i) * 1000 + nidx] = fmaxf(acc[i] + bb, 0.f);
    }
}

// out = hidden @ W2^T + b2 ; W2:(48,1000)
__global__ void __launch_bounds__(256)
fc2_kernel(const float* __restrict__ w2, const float* __restrict__ b2,
           float* __restrict__ out)
{
    __shared__ float sh[1000];
    const int nb = blockIdx.x;
    const int tid = threadIdx.x;
    for (int i = tid; i < 1000; i += 256) sh[i] = g_h[(size_t)nb * 1000 + i];
    __syncthreads();
    const int wid = tid >> 5, lane = tid & 31;
    for (int j = wid; j < 48; j += 8) {
        const float* wr = w2 + j * 1000;
        float acc = 0.f;
        for (int k = lane; k < 1000; k += 32) acc = fmaf(sh[k], wr[k], acc);
#pragma unroll
        for (int off = 16; off; off >>= 1) acc += __shfl_xor_sync(0xffffffffu, acc, off);
        if (lane == 0) out[nb * 48 + j] = acc + b2[j];
    }
}

extern "C" void kernel_launch(void* const* d_in, const int* in_sizes, int n_in,
                              void* d_out, int out_size)
{
    const float* x    = (const float*)d_in[0];
    const float* Wih0 = (const float*)d_in[1];
    const float* Wih1 = (const float*)d_in[2];
    const float* Whh1 = (const float*)d_in[3];
    const float* bih1 = (const float*)d_in[4];
    const float* bhh1 = (const float*)d_in[5];
    const float* Wih2 = (const float*)d_in[6];
    const float* Whh2 = (const float*)d_in[7];
    const float* bih2 = (const float*)d_in[8];
    const float* bhh2 = (const float*)d_in[9];
    const float* w1   = (const float*)d_in[10];
    const float* b1   = (const float*)d_in[11];
    const float* w2   = (const float*)d_in[12];
    const float* b2   = (const float*)d_in[13];
    float* out = (float*)d_out;

    const size_t smem = (size_t)(2 * TSEQ * 64 + 2 * TSEQ * 32 + 32) * sizeof(float); // 196736 B
    cudaFuncSetAttribute(lstm_kernel, cudaFuncAttributeMaxDynamicSharedMemorySize, (int)smem);

    lstm_kernel<<<NSEQ, 256, smem>>>(x, Wih0, Wih1, Whh1, bih1, bhh1,
                                     Wih2, Whh2, bih2, bhh2);
    fc1_kernel<<<dim3(8, 32), 256>>>(w1, b1);
    fc2_kernel<<<TSEQ, 256>>>(w2, b2, out);
}